// round 12
// baseline (speedup 1.0000x reference)
#include <cuda_runtime.h>
#include <cuda_bf16.h>
#include <cstdint>

// ============================================================================
// Fused LatentDynamicsModel, split-bf16 mma.sync (family-common PTX).
// R12: TM=32, 256 threads, 2 CTAs/SM (independent barrier domains overlap
// latency). Weights pre-split AND pre-transposed k-major; k16 W chunks
// double-buffered via cp.async; B fragments via ldmatrix.x4.trans.
//
//   A@B ~= Ah@Bh + Al@Bh + Ah@Bl   (fp32 accumulate, err ~1e-5)
// ============================================================================

#define TM      32
#define THREADS 256
#define BATCH   131072
#define LDA     264      // bf16 elems, activation tile stride (528B rows)
#define LDWK    264      // bf16 elems, W k-major tile stride (528B rows)
#define LDTO    264      // f32 stage stride

// ---- pre-split weight scratch (bf16 hi/lo, K-MAJOR [K][N]), elem offsets ----
#define OFF_WIN 0                               // [128][256]
#define OFF_WIH (OFF_WIN + 128 * 256)           // 3 gates x [256][256]
#define OFF_WHH (OFF_WIH + 3 * 256 * 256)
#define OFF_WO1 (OFF_WHH + 3 * 256 * 256)       // [256][256]
#define OFF_WO2 (OFF_WO1 + 256 * 256)           // [256][64]
#define W_TOTAL (OFF_WO2 + 256 * 64)

__device__ __align__(16) __nv_bfloat16 g_Whi[W_TOTAL];
__device__ __align__(16) __nv_bfloat16 g_Wlo[W_TOTAL];

// ---- smem byte offsets (total 101376 B -> 2 CTAs/SM) ----
#define OFF_XH  0                 // 32 x 264 x 2B = 16896
#define OFF_XL  16896
#define OFF_HH  33792
#define OFF_HL  50688
#define OFF_W0H 67584             // 16 x 264 x 2B = 8448 each
#define OFF_W0L 76032
#define OFF_W1H 84480
#define OFF_W1L 92928
#define SMEM_TOTAL 101376
#define OFF_TO  OFF_W0H           // epilogue f32 staging, 32x264x4 = 33792 (exact fit)

__device__ __forceinline__ uint32_t smem_to_u32(const void* p) {
    uint32_t a;
    asm("{ .reg .u64 t; cvta.to.shared.u64 t, %1; cvt.u32.u64 %0, t; }"
        : "=r"(a) : "l"(p));
    return a;
}
__device__ __forceinline__ void ldsm4(uint32_t* r, uint32_t addr) {
    asm volatile("ldmatrix.sync.aligned.m8n8.x4.shared.b16 {%0,%1,%2,%3}, [%4];"
                 : "=r"(r[0]), "=r"(r[1]), "=r"(r[2]), "=r"(r[3]) : "r"(addr));
}
__device__ __forceinline__ void ldsm4t(uint32_t* r, uint32_t addr) {
    asm volatile("ldmatrix.sync.aligned.m8n8.x4.trans.shared.b16 {%0,%1,%2,%3}, [%4];"
                 : "=r"(r[0]), "=r"(r[1]), "=r"(r[2]), "=r"(r[3]) : "r"(addr));
}
__device__ __forceinline__ void mma16816(float* d, const uint32_t* a, const uint32_t* b) {
    asm volatile("mma.sync.aligned.m16n8k16.row.col.f32.bf16.bf16.f32 "
                 "{%0,%1,%2,%3}, {%4,%5,%6,%7}, {%8,%9}, {%0,%1,%2,%3};"
                 : "+f"(d[0]), "+f"(d[1]), "+f"(d[2]), "+f"(d[3])
                 : "r"(a[0]), "r"(a[1]), "r"(a[2]), "r"(a[3]),
                   "r"(b[0]), "r"(b[1]));
}
__device__ __forceinline__ void split2(float x, float y, uint32_t& hp, uint32_t& lp) {
    __nv_bfloat16 hx = __float2bfloat16(x), hy = __float2bfloat16(y);
    float rx = x - __bfloat162float(hx), ry = y - __bfloat162float(hy);
    __nv_bfloat16 lx = __float2bfloat16(rx), ly = __float2bfloat16(ry);
    hp = ((uint32_t)__bfloat16_as_ushort(hy) << 16) | __bfloat16_as_ushort(hx);
    lp = ((uint32_t)__bfloat16_as_ushort(ly) << 16) | __bfloat16_as_ushort(lx);
}
__device__ __forceinline__ float sigm(float x) { return 1.0f / (1.0f + __expf(-x)); }

// ======================= weight conversion kernel ===========================
// Writes K-MAJOR: W'[k][n] = W[n][k], split into bf16 hi/lo.
__global__ void wconv_kernel(const float* __restrict__ W_in,
                             const float* __restrict__ W_ih,
                             const float* __restrict__ W_hh,
                             const float* __restrict__ W_o1,
                             const float* __restrict__ W_o2) {
    for (long i = (long)blockIdx.x * blockDim.x + threadIdx.x; i < W_TOTAL;
         i += (long)gridDim.x * blockDim.x) {
        float v;
        if (i < OFF_WIH) {
            long k = i >> 8, n = i & 255;
            v = (k < 66) ? W_in[n * 66 + k] : 0.0f;
        } else if (i < OFF_WHH) {
            long j = i - OFF_WIH, g = j >> 16, jj = j & 65535;
            long k = jj >> 8, n = jj & 255;
            v = W_ih[(g * 256 + n) * 256 + k];
        } else if (i < OFF_WO1) {
            long j = i - OFF_WHH, g = j >> 16, jj = j & 65535;
            long k = jj >> 8, n = jj & 255;
            v = W_hh[(g * 256 + n) * 256 + k];
        } else if (i < OFF_WO2) {
            long j = i - OFF_WO1;
            long k = j >> 8, n = j & 255;
            v = W_o1[n * 256 + k];
        } else {
            long j = i - OFF_WO2;
            long k = j >> 6, n = j & 63;
            v = W_o2[n * 256 + k];
        }
        __nv_bfloat16 h = __float2bfloat16(v);
        g_Whi[i] = h;
        g_Wlo[i] = __float2bfloat16(v - __bfloat162float(h));
    }
}

// ---------------------------------------------------------------------------
// acc[2 mi][4 ni][4] += splitA(smem) @ splitW^T, W k-major [K][NR] global.
// k16 chunks, cp.async double-buffered into [16 x LDWK] smem tiles.
// 8 warps, warp w covers cols [w*32, w*32+32), rows 0..31 (mi=2).
// ---------------------------------------------------------------------------
template <int NR>
__device__ void gemm_mma(float acc[2][4][4], uint32_t sb,
                         uint32_t offAH, uint32_t offAL,
                         const __nv_bfloat16* __restrict__ Wh,
                         const __nv_bfloat16* __restrict__ Wl,
                         int nchunks,
                         int tid, int lane, int warp_n0)
{
    constexpr int SEG = NR / 8;          // 16B segs per k-row per half
    constexpr int TOT = 16 * SEG * 2;    // transfers per chunk (hi+lo)
    constexpr int NITER = TOT / THREADS; // 4 for NR=256, 1 for NR=64

    auto issue = [&](int c, int b) {
        const uint32_t bhof = b ? OFF_W1H : OFF_W0H;
        const uint32_t blof = b ? OFF_W1L : OFF_W0L;
        #pragma unroll
        for (int it = 0; it < NITER; ++it) {
            int idx = tid + THREADS * it;       // [0, TOT)
            int half = (idx >= 16 * SEG) ? 1 : 0;
            int j = idx - half * 16 * SEG;
            int k = j / SEG, q = j % SEG;
            const __nv_bfloat16* src =
                (half ? Wl : Wh) + (long)(c * 16 + k) * NR + q * 8;
            uint32_t dst = sb + (half ? blof : bhof) + k * (LDWK * 2) + q * 16;
            asm volatile("cp.async.ca.shared.global [%0], [%1], 16;"
                         :: "r"(dst), "l"(src));
        }
        asm volatile("cp.async.commit_group;" ::: "memory");
    };

    issue(0, 0);
    for (int c = 0; c < nchunks; ++c) {
        asm volatile("cp.async.wait_group 0;" ::: "memory");
        __syncthreads();                    // chunk c visible; prev compute done
        if (c + 1 < nchunks) issue(c + 1, (c + 1) & 1);

        const uint32_t wbh = (c & 1) ? OFF_W1H : OFF_W0H;
        const uint32_t wbl = (c & 1) ? OFF_W1L : OFF_W0L;
        if (warp_n0 < NR) {
            const int mat = lane >> 3, r = lane & 7;
            // ---- A fragments (row-major tiles, full-K resident) ----
            uint32_t ah[2][4], al[2][4];
            #pragma unroll
            for (int mi = 0; mi < 2; ++mi) {
                int row = mi * 16 + (mat & 1) * 8 + r;
                int col = c * 16 + (mat >> 1) * 8;
                uint32_t off = (uint32_t)(row * LDA + col) * 2;
                ldsm4(ah[mi], sb + offAH + off);
                ldsm4(al[mi], sb + offAL + off);
            }
            // ---- B fragments (k-major tile, ldmatrix.trans) ----
            uint32_t bh[2][4], bl[2][4];
            #pragma unroll
            for (int np = 0; np < 2; ++np) {
                int krow = (mat & 1) * 8 + r;
                int ncol = warp_n0 + np * 16 + (mat >> 1) * 8;
                uint32_t boff = (uint32_t)(krow * (LDWK * 2) + ncol * 2);
                ldsm4t(bh[np], sb + wbh + boff);
                ldsm4t(bl[np], sb + wbl + boff);
            }
            // ---- 24 mmas, term-outermost ----
            #pragma unroll
            for (int t = 0; t < 3; ++t) {
                #pragma unroll
                for (int np = 0; np < 2; ++np) {
                    #pragma unroll
                    for (int hf = 0; hf < 2; ++hf) {
                        const uint32_t* bp = (t == 2 ? bl[np] : bh[np]) + 2 * hf;
                        #pragma unroll
                        for (int mi = 0; mi < 2; ++mi) {
                            const uint32_t* ap = (t == 1) ? al[mi] : ah[mi];
                            mma16816(acc[mi][2 * np + hf], ap, bp);
                        }
                    }
                }
            }
        }
    }
    __syncthreads();   // all mma reads of smem done before caller reuses tiles
}

__device__ __forceinline__ void zero_acc(float a[2][4][4]) {
    #pragma unroll
    for (int i = 0; i < 2; ++i)
        #pragma unroll
        for (int j = 0; j < 4; ++j)
            #pragma unroll
            for (int k = 0; k < 4; ++k) a[i][j][k] = 0.0f;
}

__global__ __launch_bounds__(THREADS, 2)
void ldm_kernel(const float* __restrict__ z, const float* __restrict__ action,
                const float* __restrict__ hidden,
                const float* __restrict__ b_in,
                const float* __restrict__ b_ih, const float* __restrict__ b_hh,
                const float* __restrict__ b_o1, const float* __restrict__ b_o2,
                float* __restrict__ out_z, float* __restrict__ out_h)
{
    extern __shared__ char sm[];
    const uint32_t sb = smem_to_u32(sm);
    const int tid = threadIdx.x, lane = tid & 31, warp = tid >> 5;
    const int warp_n0 = warp * 32;
    const int gid = lane >> 2, tig = lane & 3;
    const long row0 = (long)blockIdx.x * TM;

    __nv_bfloat16* XH = (__nv_bfloat16*)(sm + OFF_XH);
    __nv_bfloat16* XL = (__nv_bfloat16*)(sm + OFF_XL);
    __nv_bfloat16* HH = (__nv_bfloat16*)(sm + OFF_HH);
    __nv_bfloat16* HL = (__nv_bfloat16*)(sm + OFF_HL);

    // ---- init: za = [z|action|0] -> X cols 0..127, hidden -> H ----
    for (int i = tid; i < TM * 128; i += THREADS) {
        int r = i >> 7, c = i & 127;
        float v = 0.0f;
        if (c < 64)      v = z[(row0 + r) * 64 + c];
        else if (c < 66) v = action[(row0 + r) * 2 + (c - 64)];
        __nv_bfloat16 h = __float2bfloat16(v);
        XH[r * LDA + c] = h;
        XL[r * LDA + c] = __float2bfloat16(v - __bfloat162float(h));
    }
    for (int i = tid; i < TM * 256; i += THREADS) {
        int r = i >> 8, c = i & 255;
        float v = hidden[(row0 + r) * 256 + c];
        __nv_bfloat16 h = __float2bfloat16(v);
        HH[r * LDA + c] = h;
        HL[r * LDA + c] = __float2bfloat16(v - __bfloat162float(h));
    }
    __syncthreads();

    float acc[2][4][4], hn[2][4][4];

    // ================= P0: x = relu([z|a] @ W_in^T + b_in) =================
    zero_acc(acc);
    gemm_mma<256>(acc, sb, OFF_XH, OFF_XL,
                  g_Whi + OFF_WIN, g_Wlo + OFF_WIN, 8, tid, lane, warp_n0);
    #pragma unroll
    for (int mi = 0; mi < 2; ++mi)
        #pragma unroll
        for (int ni = 0; ni < 4; ++ni) {
            int col0 = warp_n0 + ni * 8 + tig * 2;
            int ra = mi * 16 + gid, rb = ra + 8;
            float v0 = fmaxf(acc[mi][ni][0] + b_in[col0],     0.0f);
            float v1 = fmaxf(acc[mi][ni][1] + b_in[col0 + 1], 0.0f);
            float v2 = fmaxf(acc[mi][ni][2] + b_in[col0],     0.0f);
            float v3 = fmaxf(acc[mi][ni][3] + b_in[col0 + 1], 0.0f);
            uint32_t hp, lp;
            split2(v0, v1, hp, lp);
            *(uint32_t*)(sm + OFF_XH + (ra * LDA + col0) * 2) = hp;
            *(uint32_t*)(sm + OFF_XL + (ra * LDA + col0) * 2) = lp;
            split2(v2, v3, hp, lp);
            *(uint32_t*)(sm + OFF_XH + (rb * LDA + col0) * 2) = hp;
            *(uint32_t*)(sm + OFF_XL + (rb * LDA + col0) * 2) = lp;
        }
    __syncthreads();

    // ================= P1: hn = h @ Whh_n^T + b_hh_n ========================
    zero_acc(acc);
    gemm_mma<256>(acc, sb, OFF_HH, OFF_HL,
                  g_Whi + OFF_WHH + 2 * 65536, g_Wlo + OFF_WHH + 2 * 65536, 16,
                  tid, lane, warp_n0);
    #pragma unroll
    for (int mi = 0; mi < 2; ++mi)
        #pragma unroll
        for (int ni = 0; ni < 4; ++ni) {
            int col0 = warp_n0 + ni * 8 + tig * 2;
            hn[mi][ni][0] = acc[mi][ni][0] + b_hh[512 + col0];
            hn[mi][ni][1] = acc[mi][ni][1] + b_hh[512 + col0 + 1];
            hn[mi][ni][2] = acc[mi][ni][2] + b_hh[512 + col0];
            hn[mi][ni][3] = acc[mi][ni][3] + b_hh[512 + col0 + 1];
        }

    // ================= P2: r gate; hn *= r ==================================
    zero_acc(acc);
    gemm_mma<256>(acc, sb, OFF_XH, OFF_XL,
                  g_Whi + OFF_WIH, g_Wlo + OFF_WIH, 16, tid, lane, warp_n0);
    gemm_mma<256>(acc, sb, OFF_HH, OFF_HL,
                  g_Whi + OFF_WHH, g_Wlo + OFF_WHH, 16, tid, lane, warp_n0);
    #pragma unroll
    for (int mi = 0; mi < 2; ++mi)
        #pragma unroll
        for (int ni = 0; ni < 4; ++ni) {
            int col0 = warp_n0 + ni * 8 + tig * 2;
            float b0 = b_ih[col0] + b_hh[col0];
            float b1 = b_ih[col0 + 1] + b_hh[col0 + 1];
            hn[mi][ni][0] *= sigm(acc[mi][ni][0] + b0);
            hn[mi][ni][1] *= sigm(acc[mi][ni][1] + b1);
            hn[mi][ni][2] *= sigm(acc[mi][ni][2] + b0);
            hn[mi][ni][3] *= sigm(acc[mi][ni][3] + b1);
        }

    // ================= P3: n = tanh(x@Wih_n + b + r*hn); hn = n =============
    zero_acc(acc);
    gemm_mma<256>(acc, sb, OFF_XH, OFF_XL,
                  g_Whi + OFF_WIH + 2 * 65536, g_Wlo + OFF_WIH + 2 * 65536, 16,
                  tid, lane, warp_n0);
    #pragma unroll
    for (int mi = 0; mi < 2; ++mi)
        #pragma unroll
        for (int ni = 0; ni < 4; ++ni) {
            int col0 = warp_n0 + ni * 8 + tig * 2;
            hn[mi][ni][0] = tanhf(acc[mi][ni][0] + b_ih[512 + col0]     + hn[mi][ni][0]);
            hn[mi][ni][1] = tanhf(acc[mi][ni][1] + b_ih[512 + col0 + 1] + hn[mi][ni][1]);
            hn[mi][ni][2] = tanhf(acc[mi][ni][2] + b_ih[512 + col0]     + hn[mi][ni][2]);
            hn[mi][ni][3] = tanhf(acc[mi][ni][3] + b_ih[512 + col0 + 1] + hn[mi][ni][3]);
        }

    // ================= P4: z gate; h_new ====================================
    zero_acc(acc);
    gemm_mma<256>(acc, sb, OFF_XH, OFF_XL,
                  g_Whi + OFF_WIH + 1 * 65536, g_Wlo + OFF_WIH + 1 * 65536, 16,
                  tid, lane, warp_n0);
    gemm_mma<256>(acc, sb, OFF_HH, OFF_HL,
                  g_Whi + OFF_WHH + 1 * 65536, g_Wlo + OFF_WHH + 1 * 65536, 16,
                  tid, lane, warp_n0);
    {
        float* TO = (float*)(sm + OFF_TO);
        #pragma unroll
        for (int mi = 0; mi < 2; ++mi)
            #pragma unroll
            for (int ni = 0; ni < 4; ++ni) {
                int col0 = warp_n0 + ni * 8 + tig * 2;
                int ra = mi * 16 + gid, rb = ra + 8;
                float bz0 = b_ih[256 + col0] + b_hh[256 + col0];
                float bz1 = b_ih[256 + col0 + 1] + b_hh[256 + col0 + 1];
                #pragma unroll
                for (int cc = 0; cc < 4; ++cc) {
                    int row = (cc < 2) ? ra : rb;
                    int col = col0 + (cc & 1);
                    float zg = sigm(acc[mi][ni][cc] + ((cc & 1) ? bz1 : bz0));
                    float h  = __bfloat162float(HH[row * LDA + col]) +
                               __bfloat162float(HL[row * LDA + col]);
                    TO[row * LDTO + col] = (1.0f - zg) * hn[mi][ni][cc] + zg * h;
                }
            }
        __syncthreads();
        for (int i = tid; i < TM * 256; i += THREADS) {
            int r = i >> 8, c = i & 255;
            float v = TO[r * LDTO + c];
            out_h[(row0 + r) * 256 + c] = v;
            __nv_bfloat16 h = __float2bfloat16(v);
            XH[r * LDA + c] = h;
            XL[r * LDA + c] = __float2bfloat16(v - __bfloat162float(h));
        }
        __syncthreads();
    }

    // ================= P5: y = relu(h_new @ W_o1^T + b_o1) -> H tiles =======
    zero_acc(acc);
    gemm_mma<256>(acc, sb, OFF_XH, OFF_XL,
                  g_Whi + OFF_WO1, g_Wlo + OFF_WO1, 16, tid, lane, warp_n0);
    #pragma unroll
    for (int mi = 0; mi < 2; ++mi)
        #pragma unroll
        for (int ni = 0; ni < 4; ++ni) {
            int col0 = warp_n0 + ni * 8 + tig * 2;
            int ra = mi * 16 + gid, rb = ra + 8;
            float v0 = fmaxf(acc[mi][ni][0] + b_o1[col0],     0.0f);
            float v1 = fmaxf(acc[mi][ni][1] + b_o1[col0 + 1], 0.0f);
            float v2 = fmaxf(acc[mi][ni][2] + b_o1[col0],     0.0f);
            float v3 = fmaxf(acc[mi][ni][3] + b_o1[col0 + 1], 0.0f);
            uint32_t hp, lp;
            split2(v0, v1, hp, lp);
            *(uint32_t*)(sm + OFF_HH + (ra * LDA + col0) * 2) = hp;
            *(uint32_t*)(sm + OFF_HL + (ra * LDA + col0) * 2) = lp;
            split2(v2, v3, hp, lp);
            *(uint32_t*)(sm + OFF_HH + (rb * LDA + col0) * 2) = hp;
            *(uint32_t*)(sm + OFF_HL + (rb * LDA + col0) * 2) = lp;
        }
    __syncthreads();

    // ================= P6: z_next = y @ W_o2^T + b_o2 (N=64) ================
    zero_acc(acc);
    gemm_mma<64>(acc, sb, OFF_HH, OFF_HL,
                 g_Whi + OFF_WO2, g_Wlo + OFF_WO2, 16, tid, lane, warp_n0);
    {
        float* TO = (float*)(sm + OFF_TO);
        if (warp_n0 < 64) {
            #pragma unroll
            for (int mi = 0; mi < 2; ++mi)
                #pragma unroll
                for (int ni = 0; ni < 4; ++ni) {
                    int col0 = warp_n0 + ni * 8 + tig * 2;
                    int ra = mi * 16 + gid, rb = ra + 8;
                    TO[ra * 68 + col0]     = acc[mi][ni][0] + b_o2[col0];
                    TO[ra * 68 + col0 + 1] = acc[mi][ni][1] + b_o2[col0 + 1];
                    TO[rb * 68 + col0]     = acc[mi][ni][2] + b_o2[col0];
                    TO[rb * 68 + col0 + 1] = acc[mi][ni][3] + b_o2[col0 + 1];
                }
        }
        __syncthreads();
        for (int i = tid; i < TM * 64; i += THREADS) {
            int r = i >> 6, c = i & 63;
            out_z[(row0 + r) * 64 + c] = TO[r * 68 + c];
        }
    }
}

// ============================== launch ======================================

extern "C" void kernel_launch(void* const* d_in, const int* in_sizes, int n_in,
                              void* d_out, int out_size) {
    const float* z      = (const float*)d_in[0];
    const float* action = (const float*)d_in[1];
    const float* hidden = (const float*)d_in[2];
    const float* W_in   = (const float*)d_in[3];
    const float* b_in   = (const float*)d_in[4];
    const float* W_ih   = (const float*)d_in[5];
    const float* W_hh   = (const float*)d_in[6];
    const float* b_ih   = (const float*)d_in[7];
    const float* b_hh   = (const float*)d_in[8];
    const float* W_o1   = (const float*)d_in[9];
    const float* b_o1   = (const float*)d_in[10];
    const float* W_o2   = (const float*)d_in[11];
    const float* b_o2   = (const float*)d_in[12];

    float* out_z = (float*)d_out;                       // [B, 64]
    float* out_h = (float*)d_out + (long)BATCH * 64;    // [B, 256]

    cudaFuncSetAttribute(ldm_kernel,
                         cudaFuncAttributeMaxDynamicSharedMemorySize, SMEM_TOTAL);

    wconv_kernel<<<256, 256>>>(W_in, W_ih, W_hh, W_o1, W_o2);
    dim3 grid(BATCH / TM);
    ldm_kernel<<<grid, THREADS, SMEM_TOTAL>>>(
        z, action, hidden, b_in, b_ih, b_hh, b_o1, b_o2, out_z, out_h);
}

// round 13
// speedup vs baseline: 1.0662x; 1.0662x over previous
#include <cuda_runtime.h>
#include <cuda_bf16.h>
#include <cstdint>

// ============================================================================
// Fused LatentDynamicsModel, split-bf16 mma.sync (family-common PTX).
// R13: R11 skeleton, but 8 warps x (32x64) tiles (2m x 4n) @ 256 threads.
// MAC/LDS-byte 12.3 -> 16; A-fragment redundancy 8x -> 4x; 48 independent
// mmas per warp-k16 saturate the SMSP tensor pipe from a single warp.
//
//   A@B ~= Ah@Bh + Al@Bh + Ah@Bl   (fp32 accumulate, err ~1e-5)
// ============================================================================

#define TM      64
#define THREADS 256
#define BATCH   131072
#define LDA     264      // bf16 elems, A-tile stride
#define LDTO    264      // f32 stage stride

// ---- pre-split weight scratch (bf16 hi/lo, row-major [N][K]) ----
#define OFF_WIN 0
#define OFF_WIH (OFF_WIN + 256 * 128)
#define OFF_WHH (OFF_WIH + 768 * 256)
#define OFF_WO1 (OFF_WHH + 768 * 256)
#define OFF_WO2 (OFF_WO1 + 256 * 256)
#define W_TOTAL (OFF_WO2 + 64 * 256)

__device__ __align__(16) __nv_bfloat16 g_Whi[W_TOTAL];
__device__ __align__(16) __nv_bfloat16 g_Wlo[W_TOTAL];

// ---- smem byte offsets ----
#define OFF_XH  0
#define OFF_XL  33792
#define OFF_HH  67584
#define OFF_HL  101376
#define OFF_W0H 135168            // 256 rows x 80B
#define OFF_W0L 155648
#define OFF_W1H 176128
#define OFF_W1L 196608
#define SMEM_TOTAL 217088
#define OFF_TO  OFF_W0H           // epilogue f32 staging (gemm idle)

__device__ __forceinline__ uint32_t smem_to_u32(const void* p) {
    uint32_t a;
    asm("{ .reg .u64 t; cvta.to.shared.u64 t, %1; cvt.u32.u64 %0, t; }"
        : "=r"(a) : "l"(p));
    return a;
}
__device__ __forceinline__ void ldsm4(uint32_t* r, uint32_t addr) {
    asm volatile("ldmatrix.sync.aligned.m8n8.x4.shared.b16 {%0,%1,%2,%3}, [%4];"
                 : "=r"(r[0]), "=r"(r[1]), "=r"(r[2]), "=r"(r[3]) : "r"(addr));
}
__device__ __forceinline__ void mma16816(float* d, const uint32_t* a, const uint32_t* b) {
    asm volatile("mma.sync.aligned.m16n8k16.row.col.f32.bf16.bf16.f32 "
                 "{%0,%1,%2,%3}, {%4,%5,%6,%7}, {%8,%9}, {%0,%1,%2,%3};"
                 : "+f"(d[0]), "+f"(d[1]), "+f"(d[2]), "+f"(d[3])
                 : "r"(a[0]), "r"(a[1]), "r"(a[2]), "r"(a[3]),
                   "r"(b[0]), "r"(b[1]));
}
__device__ __forceinline__ void split2(float x, float y, uint32_t& hp, uint32_t& lp) {
    __nv_bfloat16 hx = __float2bfloat16(x), hy = __float2bfloat16(y);
    float rx = x - __bfloat162float(hx), ry = y - __bfloat162float(hy);
    __nv_bfloat16 lx = __float2bfloat16(rx), ly = __float2bfloat16(ry);
    hp = ((uint32_t)__bfloat16_as_ushort(hy) << 16) | __bfloat16_as_ushort(hx);
    lp = ((uint32_t)__bfloat16_as_ushort(ly) << 16) | __bfloat16_as_ushort(lx);
}
__device__ __forceinline__ float sigm(float x) { return 1.0f / (1.0f + __expf(-x)); }

// ======================= weight conversion kernel ===========================
__global__ void wconv_kernel(const float* __restrict__ W_in,
                             const float* __restrict__ W_ih,
                             const float* __restrict__ W_hh,
                             const float* __restrict__ W_o1,
                             const float* __restrict__ W_o2) {
    for (long i = (long)blockIdx.x * blockDim.x + threadIdx.x; i < W_TOTAL;
         i += (long)gridDim.x * blockDim.x) {
        float v;
        if (i < OFF_WIH)      { long r = i >> 7, c = i & 127;
                                v = (c < 66) ? W_in[r * 66 + c] : 0.0f; }
        else if (i < OFF_WHH)   v = W_ih[i - OFF_WIH];
        else if (i < OFF_WO1)   v = W_hh[i - OFF_WHH];
        else if (i < OFF_WO2)   v = W_o1[i - OFF_WO1];
        else                    v = W_o2[i - OFF_WO2];
        __nv_bfloat16 h = __float2bfloat16(v);
        g_Whi[i] = h;
        g_Wlo[i] = __float2bfloat16(v - __bfloat162float(h));
    }
}

// ---------------------------------------------------------------------------
// acc[2 mi][8 ni][4] += splitA(smem) @ splitW(global bf16 hi/lo)^T
// Weight chunks [NR x 32] cp.async double-buffered into SMEM ping-pong.
// 8 warps, warp (warp_m, warp_n0): rows warp_m*32..+32, cols warp_n0..+64.
// Per k16: preload A (4 ldsm4) + B (8 ldsm4), then 48 mmas term-outermost.
// ---------------------------------------------------------------------------
template <int NR>
__device__ void gemm_mma(float acc[2][8][4], uint32_t sb,
                         uint32_t offAH, uint32_t offAL,
                         const __nv_bfloat16* __restrict__ Wh,
                         const __nv_bfloat16* __restrict__ Wl,
                         int ldw, int nchunks,
                         int tid, int lane, int warp_m, int warp_n0)
{
    constexpr int NITER = (NR * 8) / THREADS;   // 16B transfers per thread

    auto issue = [&](int c, int b) {
        const uint32_t bhof = b ? OFF_W1H : OFF_W0H;
        const uint32_t blof = b ? OFF_W1L : OFF_W0L;
        #pragma unroll
        for (int it = 0; it < NITER; ++it) {
            int i = tid + THREADS * it;        // [0, NR*8)
            int half = (i >= NR * 4) ? 1 : 0;  // 0=hi 1=lo
            int j = i - half * NR * 4;
            int row = j >> 2, q = j & 3;
            const __nv_bfloat16* src =
                (half ? Wl : Wh) + (long)row * ldw + c * 32 + q * 8;
            uint32_t dst = sb + (half ? blof : bhof) + row * 80 + q * 16;
            asm volatile("cp.async.ca.shared.global [%0], [%1], 16;"
                         :: "r"(dst), "l"(src));
        }
        asm volatile("cp.async.commit_group;" ::: "memory");
    };

    issue(0, 0);
    for (int c = 0; c < nchunks; ++c) {
        asm volatile("cp.async.wait_group 0;" ::: "memory");
        __syncthreads();                    // chunk c visible; prev compute done
        if (c + 1 < nchunks) issue(c + 1, (c + 1) & 1);

        const uint32_t wbh = (c & 1) ? OFF_W1H : OFF_W0H;
        const uint32_t wbl = (c & 1) ? OFF_W1L : OFF_W0L;
        if (warp_n0 < NR) {
            const int mat = lane >> 3, r = lane & 7;
            #pragma unroll
            for (int ks = 0; ks < 2; ++ks) {
                // ---- A fragments: 32 rows (2 mi), hi+lo ----
                uint32_t ah[2][4], al[2][4];
                #pragma unroll
                for (int mi = 0; mi < 2; ++mi) {
                    int row = warp_m * 32 + mi * 16 + (mat & 1) * 8 + r;
                    int col = c * 32 + ks * 16 + (mat >> 1) * 8;
                    uint32_t off = (uint32_t)(row * LDA + col) * 2;
                    ldsm4(ah[mi], sb + offAH + off);
                    ldsm4(al[mi], sb + offAL + off);
                }
                // ---- B fragments: 64 cols (4 np groups of 16), hi+lo ----
                uint32_t bh[4][4], bl[4][4];
                #pragma unroll
                for (int np = 0; np < 4; ++np) {
                    int n  = warp_n0 + (2 * np + (mat >> 1)) * 8 + r;
                    int kc = ks * 16 + (mat & 1) * 8;
                    uint32_t boff = (uint32_t)(n * 80 + kc * 2);
                    ldsm4(bh[np], sb + wbh + boff);
                    ldsm4(bl[np], sb + wbl + boff);
                }
                // ---- 48 mmas, term-outermost ----
                #pragma unroll
                for (int t = 0; t < 3; ++t) {
                    #pragma unroll
                    for (int np = 0; np < 4; ++np) {
                        #pragma unroll
                        for (int hf = 0; hf < 2; ++hf) {
                            const uint32_t* bp = (t == 2 ? bl[np] : bh[np]) + 2 * hf;
                            #pragma unroll
                            for (int mi = 0; mi < 2; ++mi) {
                                const uint32_t* ap = (t == 1) ? al[mi] : ah[mi];
                                mma16816(acc[mi][2 * np + hf], ap, bp);
                            }
                        }
                    }
                }
            }
        }
    }
    __syncthreads();   // all mma reads of smem done before caller reuses tiles
}

__device__ __forceinline__ void zero_acc(float a[2][8][4]) {
    #pragma unroll
    for (int i = 0; i < 2; ++i)
        #pragma unroll
        for (int j = 0; j < 8; ++j)
            #pragma unroll
            for (int k = 0; k < 4; ++k) a[i][j][k] = 0.0f;
}

__global__ __launch_bounds__(THREADS, 1)
void ldm_kernel(const float* __restrict__ z, const float* __restrict__ action,
                const float* __restrict__ hidden,
                const float* __restrict__ b_in,
                const float* __restrict__ b_ih, const float* __restrict__ b_hh,
                const float* __restrict__ b_o1, const float* __restrict__ b_o2,
                float* __restrict__ out_z, float* __restrict__ out_h)
{
    extern __shared__ char sm[];
    const uint32_t sb = smem_to_u32(sm);
    const int tid = threadIdx.x, lane = tid & 31, warp = tid >> 5;
    const int warp_m = warp & 1, warp_n0 = (warp >> 1) * 64;
    const int gid = lane >> 2, tig = lane & 3;
    const long row0 = (long)blockIdx.x * TM;

    __nv_bfloat16* XH = (__nv_bfloat16*)(sm + OFF_XH);
    __nv_bfloat16* XL = (__nv_bfloat16*)(sm + OFF_XL);
    __nv_bfloat16* HH = (__nv_bfloat16*)(sm + OFF_HH);
    __nv_bfloat16* HL = (__nv_bfloat16*)(sm + OFF_HL);

    // ---- init: za = [z|action|0] -> X cols 0..127, hidden -> H ----
    for (int i = tid; i < TM * 128; i += THREADS) {
        int r = i >> 7, c = i & 127;
        float v = 0.0f;
        if (c < 64)      v = z[(row0 + r) * 64 + c];
        else if (c < 66) v = action[(row0 + r) * 2 + (c - 64)];
        __nv_bfloat16 h = __float2bfloat16(v);
        XH[r * LDA + c] = h;
        XL[r * LDA + c] = __float2bfloat16(v - __bfloat162float(h));
    }
    for (int i = tid; i < TM * 256; i += THREADS) {
        int r = i >> 8, c = i & 255;
        float v = hidden[(row0 + r) * 256 + c];
        __nv_bfloat16 h = __float2bfloat16(v);
        HH[r * LDA + c] = h;
        HL[r * LDA + c] = __float2bfloat16(v - __bfloat162float(h));
    }
    __syncthreads();

    float acc[2][8][4], hn[2][8][4];

    // ================= P0: x = relu([z|a] @ W_in^T + b_in) =================
    zero_acc(acc);
    gemm_mma<256>(acc, sb, OFF_XH, OFF_XL,
                  g_Whi + OFF_WIN, g_Wlo + OFF_WIN, 128, 4,
                  tid, lane, warp_m, warp_n0);
    #pragma unroll
    for (int mi = 0; mi < 2; ++mi)
        #pragma unroll
        for (int ni = 0; ni < 8; ++ni) {
            int col0 = warp_n0 + ni * 8 + tig * 2;
            int ra = warp_m * 32 + mi * 16 + gid, rb = ra + 8;
            float v0 = fmaxf(acc[mi][ni][0] + b_in[col0],     0.0f);
            float v1 = fmaxf(acc[mi][ni][1] + b_in[col0 + 1], 0.0f);
            float v2 = fmaxf(acc[mi][ni][2] + b_in[col0],     0.0f);
            float v3 = fmaxf(acc[mi][ni][3] + b_in[col0 + 1], 0.0f);
            uint32_t hp, lp;
            split2(v0, v1, hp, lp);
            *(uint32_t*)(sm + OFF_XH + (ra * LDA + col0) * 2) = hp;
            *(uint32_t*)(sm + OFF_XL + (ra * LDA + col0) * 2) = lp;
            split2(v2, v3, hp, lp);
            *(uint32_t*)(sm + OFF_XH + (rb * LDA + col0) * 2) = hp;
            *(uint32_t*)(sm + OFF_XL + (rb * LDA + col0) * 2) = lp;
        }
    __syncthreads();

    // ================= P1: hn = h @ Whh_n^T + b_hh_n ========================
    zero_acc(acc);
    gemm_mma<256>(acc, sb, OFF_HH, OFF_HL,
                  g_Whi + OFF_WHH + 512 * 256, g_Wlo + OFF_WHH + 512 * 256, 256, 8,
                  tid, lane, warp_m, warp_n0);
    #pragma unroll
    for (int mi = 0; mi < 2; ++mi)
        #pragma unroll
        for (int ni = 0; ni < 8; ++ni) {
            int col0 = warp_n0 + ni * 8 + tig * 2;
            hn[mi][ni][0] = acc[mi][ni][0] + b_hh[512 + col0];
            hn[mi][ni][1] = acc[mi][ni][1] + b_hh[512 + col0 + 1];
            hn[mi][ni][2] = acc[mi][ni][2] + b_hh[512 + col0];
            hn[mi][ni][3] = acc[mi][ni][3] + b_hh[512 + col0 + 1];
        }

    // ================= P2: r gate; hn *= r ==================================
    zero_acc(acc);
    gemm_mma<256>(acc, sb, OFF_XH, OFF_XL,
                  g_Whi + OFF_WIH, g_Wlo + OFF_WIH, 256, 8,
                  tid, lane, warp_m, warp_n0);
    gemm_mma<256>(acc, sb, OFF_HH, OFF_HL,
                  g_Whi + OFF_WHH, g_Wlo + OFF_WHH, 256, 8,
                  tid, lane, warp_m, warp_n0);
    #pragma unroll
    for (int mi = 0; mi < 2; ++mi)
        #pragma unroll
        for (int ni = 0; ni < 8; ++ni) {
            int col0 = warp_n0 + ni * 8 + tig * 2;
            float b0 = b_ih[col0] + b_hh[col0];
            float b1 = b_ih[col0 + 1] + b_hh[col0 + 1];
            hn[mi][ni][0] *= sigm(acc[mi][ni][0] + b0);
            hn[mi][ni][1] *= sigm(acc[mi][ni][1] + b1);
            hn[mi][ni][2] *= sigm(acc[mi][ni][2] + b0);
            hn[mi][ni][3] *= sigm(acc[mi][ni][3] + b1);
        }

    // ================= P3: n = tanh(x@Wih_n + b + r*hn); hn = n =============
    zero_acc(acc);
    gemm_mma<256>(acc, sb, OFF_XH, OFF_XL,
                  g_Whi + OFF_WIH + 512 * 256, g_Wlo + OFF_WIH + 512 * 256, 256, 8,
                  tid, lane, warp_m, warp_n0);
    #pragma unroll
    for (int mi = 0; mi < 2; ++mi)
        #pragma unroll
        for (int ni = 0; ni < 8; ++ni) {
            int col0 = warp_n0 + ni * 8 + tig * 2;
            hn[mi][ni][0] = tanhf(acc[mi][ni][0] + b_ih[512 + col0]     + hn[mi][ni][0]);
            hn[mi][ni][1] = tanhf(acc[mi][ni][1] + b_ih[512 + col0 + 1] + hn[mi][ni][1]);
            hn[mi][ni][2] = tanhf(acc[mi][ni][2] + b_ih[512 + col0]     + hn[mi][ni][2]);
            hn[mi][ni][3] = tanhf(acc[mi][ni][3] + b_ih[512 + col0 + 1] + hn[mi][ni][3]);
        }

    // ================= P4: z gate; h_new ====================================
    zero_acc(acc);
    gemm_mma<256>(acc, sb, OFF_XH, OFF_XL,
                  g_Whi + OFF_WIH + 256 * 256, g_Wlo + OFF_WIH + 256 * 256, 256, 8,
                  tid, lane, warp_m, warp_n0);
    gemm_mma<256>(acc, sb, OFF_HH, OFF_HL,
                  g_Whi + OFF_WHH + 256 * 256, g_Wlo + OFF_WHH + 256 * 256, 256, 8,
                  tid, lane, warp_m, warp_n0);
    {
        float* TO = (float*)(sm + OFF_TO);
        #pragma unroll
        for (int mi = 0; mi < 2; ++mi)
            #pragma unroll
            for (int ni = 0; ni < 8; ++ni) {
                int col0 = warp_n0 + ni * 8 + tig * 2;
                int ra = warp_m * 32 + mi * 16 + gid, rb = ra + 8;
                float bz0 = b_ih[256 + col0] + b_hh[256 + col0];
                float bz1 = b_ih[256 + col0 + 1] + b_hh[256 + col0 + 1];
                #pragma unroll
                for (int cc = 0; cc < 4; ++cc) {
                    int row = (cc < 2) ? ra : rb;
                    int col = col0 + (cc & 1);
                    float zg = sigm(acc[mi][ni][cc] + ((cc & 1) ? bz1 : bz0));
                    float h  = __bfloat162float(HH[row * LDA + col]) +
                               __bfloat162float(HL[row * LDA + col]);
                    TO[row * LDTO + col] = (1.0f - zg) * hn[mi][ni][cc] + zg * h;
                }
            }
        __syncthreads();
        for (int i = tid; i < TM * 256; i += THREADS) {
            int r = i >> 8, c = i & 255;
            float v = TO[r * LDTO + c];
            out_h[(row0 + r) * 256 + c] = v;
            __nv_bfloat16 h = __float2bfloat16(v);
            XH[r * LDA + c] = h;
            XL[r * LDA + c] = __float2bfloat16(v - __bfloat162float(h));
        }
        __syncthreads();
    }

    // ================= P5: y = relu(h_new @ W_o1^T + b_o1) -> H tiles =======
    zero_acc(acc);
    gemm_mma<256>(acc, sb, OFF_XH, OFF_XL,
                  g_Whi + OFF_WO1, g_Wlo + OFF_WO1, 256, 8,
                  tid, lane, warp_m, warp_n0);
    #pragma unroll
    for (int mi = 0; mi < 2; ++mi)
        #pragma unroll
        for (int ni = 0; ni < 8; ++ni) {
            int col0 = warp_n0 + ni * 8 + tig * 2;
            int ra = warp_m * 32 + mi * 16 + gid, rb = ra + 8;
            float v0 = fmaxf(acc[mi][ni][0] + b_o1[col0],     0.0f);
            float v1 = fmaxf(acc[mi][ni][1] + b_o1[col0 + 1], 0.0f);
            float v2 = fmaxf(acc[mi][ni][2] + b_o1[col0],     0.0f);
            float v3 = fmaxf(acc[mi][ni][3] + b_o1[col0 + 1], 0.0f);
            uint32_t hp, lp;
            split2(v0, v1, hp, lp);
            *(uint32_t*)(sm + OFF_HH + (ra * LDA + col0) * 2) = hp;
            *(uint32_t*)(sm + OFF_HL + (ra * LDA + col0) * 2) = lp;
            split2(v2, v3, hp, lp);
            *(uint32_t*)(sm + OFF_HH + (rb * LDA + col0) * 2) = hp;
            *(uint32_t*)(sm + OFF_HL + (rb * LDA + col0) * 2) = lp;
        }
    __syncthreads();

    // ================= P6: z_next = y @ W_o2^T + b_o2 (N=64) ================
    zero_acc(acc);
    gemm_mma<64>(acc, sb, OFF_HH, OFF_HL,
                 g_Whi + OFF_WO2, g_Wlo + OFF_WO2, 256, 8,
                 tid, lane, warp_m, warp_n0);
    {
        float* TO = (float*)(sm + OFF_TO);
        if (warp_n0 < 64) {
            #pragma unroll
            for (int mi = 0; mi < 2; ++mi)
                #pragma unroll
                for (int ni = 0; ni < 8; ++ni) {
                    int col0 = warp_n0 + ni * 8 + tig * 2;
                    int ra = warp_m * 32 + mi * 16 + gid, rb = ra + 8;
                    TO[ra * 68 + col0]     = acc[mi][ni][0] + b_o2[col0];
                    TO[ra * 68 + col0 + 1] = acc[mi][ni][1] + b_o2[col0 + 1];
                    TO[rb * 68 + col0]     = acc[mi][ni][2] + b_o2[col0];
                    TO[rb * 68 + col0 + 1] = acc[mi][ni][3] + b_o2[col0 + 1];
                }
        }
        __syncthreads();
        for (int i = tid; i < TM * 64; i += THREADS) {
            int r = i >> 6, c = i & 63;
            out_z[(row0 + r) * 64 + c] = TO[r * 68 + c];
        }
    }
}

// ============================== launch ======================================

extern "C" void kernel_launch(void* const* d_in, const int* in_sizes, int n_in,
                              void* d_out, int out_size) {
    const float* z      = (const float*)d_in[0];
    const float* action = (const float*)d_in[1];
    const float* hidden = (const float*)d_in[2];
    const float* W_in   = (const float*)d_in[3];
    const float* b_in   = (const float*)d_in[4];
    const float* W_ih   = (const float*)d_in[5];
    const float* W_hh   = (const float*)d_in[6];
    const float* b_ih   = (const float*)d_in[7];
    const float* b_hh   = (const float*)d_in[8];
    const float* W_o1   = (const float*)d_in[9];
    const float* b_o1   = (const float*)d_in[10];
    const float* W_o2   = (const float*)d_in[11];
    const float* b_o2   = (const float*)d_in[12];

    float* out_z = (float*)d_out;                       // [B, 64]
    float* out_h = (float*)d_out + (long)BATCH * 64;    // [B, 256]

    cudaFuncSetAttribute(ldm_kernel,
                         cudaFuncAttributeMaxDynamicSharedMemorySize, SMEM_TOTAL);

    wconv_kernel<<<256, 256>>>(W_in, W_ih, W_hh, W_o1, W_o2);
    dim3 grid(BATCH / TM);
    ldm_kernel<<<grid, THREADS, SMEM_TOTAL>>>(
        z, action, hidden, b_in, b_ih, b_hh, b_o1, b_o2, out_z, out_h);
}

// round 14
// speedup vs baseline: 2.5869x; 2.4264x over previous
#include <cuda_runtime.h>
#include <cuda_fp16.h>
#include <cstdint>

// ============================================================================
// Fused LatentDynamicsModel, single-pass fp16 mma.sync (family-common PTX).
// R14: fp16 (11-bit mantissa) single term replaces bf16 3-term split ->
// 3x fewer HMMA (the saturated pipe), 2x less LDS + weight traffic.
// 4-stage cp.async weight pipeline (wait_group 2, tail-aware).
// Expected rel_err ~1e-4 (fp16 input rounding, fp32 accumulate).
//
// Per CTA: 64 batch rows, 512 threads, 16 warps of 32x32 tiles (2m x 8n).
// Phases: P0 x=relu([z|a]W_in^T+b)   P1 hn=h Whh_n^T+b
//         P2 r gate; hn*=r           P3 n=tanh(xWih_n+b+hn); hn=n
//         P4 z gate; h_new->out_h    P5 y=relu(h_new W_o1^T+b)
//         P6 z'=y W_o2^T+b->out_z
// ============================================================================

#define TM      64
#define THREADS 512
#define BATCH   131072
#define LDA     264      // fp16 elems, activation tile stride (528B rows)
#define LDTO    264      // f32 stage stride

// ---- pre-converted fp16 weights (row-major [N][K], W_in padded K66->128) ----
#define OFF_WIN 0
#define OFF_WIH (OFF_WIN + 256 * 128)
#define OFF_WHH (OFF_WIH + 768 * 256)
#define OFF_WO1 (OFF_WHH + 768 * 256)
#define OFF_WO2 (OFF_WO1 + 256 * 256)
#define W_TOTAL (OFF_WO2 + 64 * 256)

__device__ __align__(16) __half g_W[W_TOTAL];

// ---- smem byte offsets ----
#define OFF_XH  0                 // 64 x 264 x 2B = 33792
#define OFF_HH  33792
#define OFF_W   67584             // 4 stages x (256 rows x 80B) = 81920
#define WSTAGE  20480
#define SMEM_TOTAL (67584 + 4 * WSTAGE)   // 149504
#define OFF_TO  OFF_W             // epilogue f32 staging (64x264x4 = 67584 fits)

__device__ __forceinline__ uint32_t smem_to_u32(const void* p) {
    uint32_t a;
    asm("{ .reg .u64 t; cvta.to.shared.u64 t, %1; cvt.u32.u64 %0, t; }"
        : "=r"(a) : "l"(p));
    return a;
}
__device__ __forceinline__ void ldsm4(uint32_t* r, uint32_t addr) {
    asm volatile("ldmatrix.sync.aligned.m8n8.x4.shared.b16 {%0,%1,%2,%3}, [%4];"
                 : "=r"(r[0]), "=r"(r[1]), "=r"(r[2]), "=r"(r[3]) : "r"(addr));
}
__device__ __forceinline__ void mma16816(float* d, const uint32_t* a, const uint32_t* b) {
    asm volatile("mma.sync.aligned.m16n8k16.row.col.f32.f16.f16.f32 "
                 "{%0,%1,%2,%3}, {%4,%5,%6,%7}, {%8,%9}, {%0,%1,%2,%3};"
                 : "+f"(d[0]), "+f"(d[1]), "+f"(d[2]), "+f"(d[3])
                 : "r"(a[0]), "r"(a[1]), "r"(a[2]), "r"(a[3]),
                   "r"(b[0]), "r"(b[1]));
}
__device__ __forceinline__ uint32_t pack2h(float x, float y) {
    __half2 h = __floats2half2_rn(x, y);
    return *reinterpret_cast<uint32_t*>(&h);
}
__device__ __forceinline__ float sigm(float x) { return 1.0f / (1.0f + __expf(-x)); }

// ======================= weight conversion kernel ===========================
__global__ void wconv_kernel(const float* __restrict__ W_in,
                             const float* __restrict__ W_ih,
                             const float* __restrict__ W_hh,
                             const float* __restrict__ W_o1,
                             const float* __restrict__ W_o2) {
    for (long i = (long)blockIdx.x * blockDim.x + threadIdx.x; i < W_TOTAL;
         i += (long)gridDim.x * blockDim.x) {
        float v;
        if (i < OFF_WIH)      { long r = i >> 7, c = i & 127;
                                v = (c < 66) ? W_in[r * 66 + c] : 0.0f; }
        else if (i < OFF_WHH)   v = W_ih[i - OFF_WIH];
        else if (i < OFF_WO1)   v = W_hh[i - OFF_WHH];
        else if (i < OFF_WO2)   v = W_o1[i - OFF_WO1];
        else                    v = W_o2[i - OFF_WO2];
        g_W[i] = __float2half_rn(v);
    }
}

// ---------------------------------------------------------------------------
// acc[2 mi][4 ni][4] += A(fp16 smem) @ W(fp16 global)^T
// Weight chunks [NR x 32] via 4-stage cp.async pipeline (3 in flight).
// 16 warps, warp (warp_m, warp_n0): rows warp_m*32..+32, cols warp_n0..+32.
// ---------------------------------------------------------------------------
template <int NR>
__device__ void gemm_mma(float acc[2][4][4], uint32_t sb, uint32_t offA,
                         const __half* __restrict__ Wg, int ldw, int nchunks,
                         int tid, int lane, int warp_m, int warp_n0)
{
    constexpr int TOT   = NR * 4;                      // 16B transfers per chunk
    constexpr int NITER = (TOT + THREADS - 1) / THREADS;

    auto issue = [&](int c) {
        uint32_t base = sb + OFF_W + (uint32_t)(c & 3) * WSTAGE;
        #pragma unroll
        for (int it = 0; it < NITER; ++it) {
            int idx = tid + THREADS * it;
            if ((TOT % THREADS == 0) || (idx < TOT)) {
                int row = idx >> 2, q = idx & 3;
                const __half* src = Wg + (long)row * ldw + c * 32 + q * 8;
                uint32_t dst = base + row * 80 + q * 16;
                asm volatile("cp.async.ca.shared.global [%0], [%1], 16;"
                             :: "r"(dst), "l"(src));
            }
        }
        asm volatile("cp.async.commit_group;" ::: "memory");
    };

    issue(0); issue(1); issue(2);                      // nchunks >= 4 always
    for (int c = 0; c < nchunks; ++c) {
        // chunk c complete <=> pending groups <= min(2, nchunks-c-1)
        int w = nchunks - 1 - c;
        if (w >= 2)      asm volatile("cp.async.wait_group 2;" ::: "memory");
        else if (w == 1) asm volatile("cp.async.wait_group 1;" ::: "memory");
        else             asm volatile("cp.async.wait_group 0;" ::: "memory");
        __syncthreads();                // chunk c visible; prev compute done
        if (c + 3 < nchunks) issue(c + 3);

        const uint32_t wb = sb + OFF_W + (uint32_t)(c & 3) * WSTAGE;
        if (warp_n0 < NR) {
            const int mat = lane >> 3, r = lane & 7;
            #pragma unroll
            for (int ks = 0; ks < 2; ++ks) {
                uint32_t a[2][4], b[2][4];
                #pragma unroll
                for (int mi = 0; mi < 2; ++mi) {
                    int row = warp_m * 32 + mi * 16 + (mat & 1) * 8 + r;
                    int col = c * 32 + ks * 16 + (mat >> 1) * 8;
                    ldsm4(a[mi], sb + offA + (uint32_t)(row * LDA + col) * 2);
                }
                #pragma unroll
                for (int np = 0; np < 2; ++np) {
                    int n  = warp_n0 + (2 * np + (mat >> 1)) * 8 + r;
                    int kc = ks * 16 + (mat & 1) * 8;
                    ldsm4(b[np], wb + (uint32_t)(n * 80 + kc * 2));
                }
                #pragma unroll
                for (int np = 0; np < 2; ++np)
                    #pragma unroll
                    for (int hf = 0; hf < 2; ++hf)
                        #pragma unroll
                        for (int mi = 0; mi < 2; ++mi)
                            mma16816(acc[mi][2 * np + hf], a[mi], b[np] + 2 * hf);
            }
        }
    }
    __syncthreads();   // all mma reads of smem done before caller reuses tiles
}

__device__ __forceinline__ void zero_acc(float a[2][4][4]) {
    #pragma unroll
    for (int i = 0; i < 2; ++i)
        #pragma unroll
        for (int j = 0; j < 4; ++j)
            #pragma unroll
            for (int k = 0; k < 4; ++k) a[i][j][k] = 0.0f;
}

__global__ __launch_bounds__(THREADS, 1)
void ldm_kernel(const float* __restrict__ z, const float* __restrict__ action,
                const float* __restrict__ hidden,
                const float* __restrict__ b_in,
                const float* __restrict__ b_ih, const float* __restrict__ b_hh,
                const float* __restrict__ b_o1, const float* __restrict__ b_o2,
                float* __restrict__ out_z, float* __restrict__ out_h)
{
    extern __shared__ char sm[];
    const uint32_t sb = smem_to_u32(sm);
    const int tid = threadIdx.x, lane = tid & 31, warp = tid >> 5;
    const int warp_m = warp & 1, warp_n0 = (warp >> 1) * 32;
    const int gid = lane >> 2, tig = lane & 3;
    const long row0 = (long)blockIdx.x * TM;

    __half* XH = (__half*)(sm + OFF_XH);
    __half* HH = (__half*)(sm + OFF_HH);

    // ---- init: za = [z|action|0] -> X cols 0..127, hidden -> H ----
    for (int i = tid; i < TM * 128; i += THREADS) {
        int r = i >> 7, c = i & 127;
        float v = 0.0f;
        if (c < 64)      v = z[(row0 + r) * 64 + c];
        else if (c < 66) v = action[(row0 + r) * 2 + (c - 64)];
        XH[r * LDA + c] = __float2half_rn(v);
    }
    for (int i = tid; i < TM * 256; i += THREADS) {
        int r = i >> 8, c = i & 255;
        HH[r * LDA + c] = __float2half_rn(hidden[(row0 + r) * 256 + c]);
    }
    __syncthreads();

    float acc[2][4][4], hn[2][4][4];

    // ================= P0: x = relu([z|a] @ W_in^T + b_in) =================
    zero_acc(acc);
    gemm_mma<256>(acc, sb, OFF_XH, g_W + OFF_WIN, 128, 4,
                  tid, lane, warp_m, warp_n0);
    #pragma unroll
    for (int mi = 0; mi < 2; ++mi)
        #pragma unroll
        for (int ni = 0; ni < 4; ++ni) {
            int col0 = warp_n0 + ni * 8 + tig * 2;
            int ra = warp_m * 32 + mi * 16 + gid, rb = ra + 8;
            float v0 = fmaxf(acc[mi][ni][0] + b_in[col0],     0.0f);
            float v1 = fmaxf(acc[mi][ni][1] + b_in[col0 + 1], 0.0f);
            float v2 = fmaxf(acc[mi][ni][2] + b_in[col0],     0.0f);
            float v3 = fmaxf(acc[mi][ni][3] + b_in[col0 + 1], 0.0f);
            *(uint32_t*)(sm + OFF_XH + (ra * LDA + col0) * 2) = pack2h(v0, v1);
            *(uint32_t*)(sm + OFF_XH + (rb * LDA + col0) * 2) = pack2h(v2, v3);
        }
    __syncthreads();

    // ================= P1: hn = h @ Whh_n^T + b_hh_n ========================
    zero_acc(acc);
    gemm_mma<256>(acc, sb, OFF_HH, g_W + OFF_WHH + 512 * 256, 256, 8,
                  tid, lane, warp_m, warp_n0);
    #pragma unroll
    for (int mi = 0; mi < 2; ++mi)
        #pragma unroll
        for (int ni = 0; ni < 4; ++ni) {
            int col0 = warp_n0 + ni * 8 + tig * 2;
            hn[mi][ni][0] = acc[mi][ni][0] + b_hh[512 + col0];
            hn[mi][ni][1] = acc[mi][ni][1] + b_hh[512 + col0 + 1];
            hn[mi][ni][2] = acc[mi][ni][2] + b_hh[512 + col0];
            hn[mi][ni][3] = acc[mi][ni][3] + b_hh[512 + col0 + 1];
        }

    // ================= P2: r gate; hn *= r ==================================
    zero_acc(acc);
    gemm_mma<256>(acc, sb, OFF_XH, g_W + OFF_WIH, 256, 8,
                  tid, lane, warp_m, warp_n0);
    gemm_mma<256>(acc, sb, OFF_HH, g_W + OFF_WHH, 256, 8,
                  tid, lane, warp_m, warp_n0);
    #pragma unroll
    for (int mi = 0; mi < 2; ++mi)
        #pragma unroll
        for (int ni = 0; ni < 4; ++ni) {
            int col0 = warp_n0 + ni * 8 + tig * 2;
            float b0 = b_ih[col0] + b_hh[col0];
            float b1 = b_ih[col0 + 1] + b_hh[col0 + 1];
            hn[mi][ni][0] *= sigm(acc[mi][ni][0] + b0);
            hn[mi][ni][1] *= sigm(acc[mi][ni][1] + b1);
            hn[mi][ni][2] *= sigm(acc[mi][ni][2] + b0);
            hn[mi][ni][3] *= sigm(acc[mi][ni][3] + b1);
        }

    // ================= P3: n = tanh(x@Wih_n + b + r*hn); hn = n =============
    zero_acc(acc);
    gemm_mma<256>(acc, sb, OFF_XH, g_W + OFF_WIH + 512 * 256, 256, 8,
                  tid, lane, warp_m, warp_n0);
    #pragma unroll
    for (int mi = 0; mi < 2; ++mi)
        #pragma unroll
        for (int ni = 0; ni < 4; ++ni) {
            int col0 = warp_n0 + ni * 8 + tig * 2;
            hn[mi][ni][0] = tanhf(acc[mi][ni][0] + b_ih[512 + col0]     + hn[mi][ni][0]);
            hn[mi][ni][1] = tanhf(acc[mi][ni][1] + b_ih[512 + col0 + 1] + hn[mi][ni][1]);
            hn[mi][ni][2] = tanhf(acc[mi][ni][2] + b_ih[512 + col0]     + hn[mi][ni][2]);
            hn[mi][ni][3] = tanhf(acc[mi][ni][3] + b_ih[512 + col0 + 1] + hn[mi][ni][3]);
        }

    // ================= P4: z gate; h_new ====================================
    zero_acc(acc);
    gemm_mma<256>(acc, sb, OFF_XH, g_W + OFF_WIH + 256 * 256, 256, 8,
                  tid, lane, warp_m, warp_n0);
    gemm_mma<256>(acc, sb, OFF_HH, g_W + OFF_WHH + 256 * 256, 256, 8,
                  tid, lane, warp_m, warp_n0);
    {
        float* TO = (float*)(sm + OFF_TO);
        #pragma unroll
        for (int mi = 0; mi < 2; ++mi)
            #pragma unroll
            for (int ni = 0; ni < 4; ++ni) {
                int col0 = warp_n0 + ni * 8 + tig * 2;
                int ra = warp_m * 32 + mi * 16 + gid, rb = ra + 8;
                float bz0 = b_ih[256 + col0] + b_hh[256 + col0];
                float bz1 = b_ih[256 + col0 + 1] + b_hh[256 + col0 + 1];
                #pragma unroll
                for (int cc = 0; cc < 4; ++cc) {
                    int row = (cc < 2) ? ra : rb;
                    int col = col0 + (cc & 1);
                    float zg = sigm(acc[mi][ni][cc] + ((cc & 1) ? bz1 : bz0));
                    float h  = hidden[(row0 + row) * 256 + col];  // full precision
                    TO[row * LDTO + col] = (1.0f - zg) * hn[mi][ni][cc] + zg * h;
                }
            }
        __syncthreads();
        for (int i = tid; i < TM * 256; i += THREADS) {
            int r = i >> 8, c = i & 255;
            float v = TO[r * LDTO + c];
            out_h[(row0 + r) * 256 + c] = v;
            XH[r * LDA + c] = __float2half_rn(v);
        }
        __syncthreads();
    }

    // ================= P5: y = relu(h_new @ W_o1^T + b_o1) -> H tiles =======
    zero_acc(acc);
    gemm_mma<256>(acc, sb, OFF_XH, g_W + OFF_WO1, 256, 8,
                  tid, lane, warp_m, warp_n0);
    #pragma unroll
    for (int mi = 0; mi < 2; ++mi)
        #pragma unroll
        for (int ni = 0; ni < 4; ++ni) {
            int col0 = warp_n0 + ni * 8 + tig * 2;
            int ra = warp_m * 32 + mi * 16 + gid, rb = ra + 8;
            float v0 = fmaxf(acc[mi][ni][0] + b_o1[col0],     0.0f);
            float v1 = fmaxf(acc[mi][ni][1] + b_o1[col0 + 1], 0.0f);
            float v2 = fmaxf(acc[mi][ni][2] + b_o1[col0],     0.0f);
            float v3 = fmaxf(acc[mi][ni][3] + b_o1[col0 + 1], 0.0f);
            *(uint32_t*)(sm + OFF_HH + (ra * LDA + col0) * 2) = pack2h(v0, v1);
            *(uint32_t*)(sm + OFF_HH + (rb * LDA + col0) * 2) = pack2h(v2, v3);
        }
    __syncthreads();

    // ================= P6: z_next = y @ W_o2^T + b_o2 (N=64) ================
    zero_acc(acc);
    gemm_mma<64>(acc, sb, OFF_HH, g_W + OFF_WO2, 256, 8,
                 tid, lane, warp_m, warp_n0);
    {
        float* TO = (float*)(sm + OFF_TO);
        if (warp_n0 < 64) {
            #pragma unroll
            for (int mi = 0; mi < 2; ++mi)
                #pragma unroll
                for (int ni = 0; ni < 4; ++ni) {
                    int col0 = warp_n0 + ni * 8 + tig * 2;
                    int ra = warp_m * 32 + mi * 16 + gid, rb = ra + 8;
                    TO[ra * 68 + col0]     = acc[mi][ni][0] + b_o2[col0];
                    TO[ra * 68 + col0 + 1] = acc[mi][ni][1] + b_o2[col0 + 1];
                    TO[rb * 68 + col0]     = acc[mi][ni][2] + b_o2[col0];
                    TO[rb * 68 + col0 + 1] = acc[mi][ni][3] + b_o2[col0 + 1];
                }
        }
        __syncthreads();
        for (int i = tid; i < TM * 64; i += THREADS) {
            int r = i >> 6, c = i & 63;
            out_z[(row0 + r) * 64 + c] = TO[r * 68 + c];
        }
    }
}

// ============================== launch ======================================

extern "C" void kernel_launch(void* const* d_in, const int* in_sizes, int n_in,
                              void* d_out, int out_size) {
    const float* z      = (const float*)d_in[0];
    const float* action = (const float*)d_in[1];
    const float* hidden = (const float*)d_in[2];
    const float* W_in   = (const float*)d_in[3];
    const float* b_in   = (const float*)d_in[4];
    const float* W_ih   = (const float*)d_in[5];
    const float* W_hh   = (const float*)d_in[6];
    const float* b_ih   = (const float*)d_in[7];
    const float* b_hh   = (const float*)d_in[8];
    const float* W_o1   = (const float*)d_in[9];
    const float* b_o1   = (const float*)d_in[10];
    const float* W_o2   = (const float*)d_in[11];
    const float* b_o2   = (const float*)d_in[12];

    float* out_z = (float*)d_out;                       // [B, 64]
    float* out_h = (float*)d_out + (long)BATCH * 64;    // [B, 256]

    cudaFuncSetAttribute(ldm_kernel,
                         cudaFuncAttributeMaxDynamicSharedMemorySize, SMEM_TOTAL);

    wconv_kernel<<<256, 256>>>(W_in, W_ih, W_hh, W_o1, W_o2);
    dim3 grid(BATCH / TM);
    ldm_kernel<<<grid, THREADS, SMEM_TOTAL>>>(
        z, action, hidden, b_in, b_ih, b_hh, b_o1, b_o2, out_z, out_h);
}